// round 10
// baseline (speedup 1.0000x reference)
#include <cuda_runtime.h>

#define NPTS   8192
#define NB     2
#define KNN    10
#define K2     11               /* KNN + self slot                    */
#define QPB    128              /* queries per CTA                    */
#define SPLIT  8                /* threads per query                  */
#define BLOCK  (QPB * SPLIT)    /* 1024                               */
#define LSUB   (NPTS / SPLIT)   /* 1024 candidates per thread         */
#define BPB    (NPTS / QPB)     /* 64 blocks per batch                */
#define NBLOCKS (NB * BPB)      /* 128 total blocks                   */
#define VEC    8

#define SMEM_SP_BYTES  (NPTS * 16)                        /* 131072 */
#define SMEM_LIST_U32  (QPB * (SPLIT - 1) * K2)           /* 9856   */
#define SMEM_TOTAL     (SMEM_SP_BYTES + SMEM_LIST_U32 * 4)

__device__ float g_partial[NBLOCKS];

__device__ __forceinline__ void net_insert(unsigned nd[K2], unsigned ck)
{
    bool tk[K2];
#pragma unroll
    for (int t = 0; t < K2; ++t) tk[t] = ck < nd[t];
#pragma unroll
    for (int t = K2 - 1; t >= 1; --t)
        nd[t] = tk[t] ? (tk[t-1] ? nd[t-1] : ck) : nd[t];
    nd[0] = tk[0] ? ck : nd[0];
}

__global__ void __launch_bounds__(BLOCK, 1) knn_lap_kernel(
    const float* __restrict__ p1, const float* __restrict__ p2)
{
    extern __shared__ char smem_raw[];
    float4*   sp    = (float4*)smem_raw;                  // 8192 * 16B = 128 KB
    unsigned* slist = (unsigned*)(smem_raw + SMEM_SP_BYTES);

    const int b = blockIdx.y;
    const float* base1 = p1 + (size_t)b * NPTS * 3;
    const float* base2 = p2 + (size_t)b * NPTS * 3;

    // Stage full batch-b point1 cloud into shared memory as (x,y,z,|p|^2).
    for (int j = threadIdx.x; j < NPTS; j += BLOCK) {
        float x = base1[3*j+0];
        float y = base1[3*j+1];
        float z = base1[3*j+2];
        sp[j] = make_float4(x, y, z, fmaf(x, x, fmaf(y, y, z*z)));
    }
    __syncthreads();

    const int tq  = threadIdx.x & (QPB - 1);   // query slot within CTA
    const int sub = threadIdx.x >> 7;          // substream 0..7
    const int qi  = blockIdx.x * QPB + tq;     // global query index
    const float4 q = sp[qi];
    const float n2x = -2.0f * q.x, n2y = -2.0f * q.y, n2z = -2.0f * q.z;
    const float qw  = q.w;

    // K2-smallest keys over this substream. key = bits(full d^2) with low 13
    // mantissa bits replaced by candidate index (keys unique, order ~ distance).
    // Self has d^2 == 0 exactly -> key == qi -> always global min.
    unsigned nd[K2];
#pragma unroll
    for (int t = 0; t < K2; ++t) nd[t] = 0xFFFFFFFFu;
    unsigned thresh = 0xFFFFFFFFu;

    const int jbeg = sub * LSUB;
    const int jend = jbeg + LSUB;
    for (int j0 = jbeg; j0 < jend; j0 += VEC) {
        unsigned key[VEC];
#pragma unroll
        for (int u = 0; u < VEC; ++u) {
            float4 c = sp[j0 + u];
            float d2 = fmaf(n2x, c.x, fmaf(n2y, c.y, fmaf(n2z, c.z, c.w + qw)));
            d2 = fmaxf(d2, 0.0f);
            key[u] = (__float_as_uint(d2) & 0xFFFFE000u) | (unsigned)(j0 + u);
        }
        unsigned m0 = min(key[0], key[1]);
        unsigned m1 = min(key[2], key[3]);
        unsigned m2 = min(key[4], key[5]);
        unsigned m3 = min(key[6], key[7]);
        unsigned mn = min(min(m0, m1), min(m2, m3));

        while (mn < thresh) {            // ~1 trip per insert event
            net_insert(nd, mn);
            thresh = nd[K2-1];
#pragma unroll
            for (int u = 0; u < VEC; ++u)         // mask inserted key (unique)
                key[u] = (key[u] == mn) ? 0xFFFFFFFFu : key[u];
            m0 = min(key[0], key[1]);
            m1 = min(key[2], key[3]);
            m2 = min(key[4], key[5]);
            m3 = min(key[6], key[7]);
            mn = min(min(m0, m1), min(m2, m3));
        }
    }

    // Substreams 1..7 publish; substream 0 merges 7*K2 foreign keys.
    if (sub) {
#pragma unroll
        for (int t = 0; t < K2; ++t)
            slist[((sub - 1) * QPB + tq) * K2 + t] = nd[t];
    }
    __syncthreads();

    float acc = 0.0f;
    if (sub == 0) {
        for (int s = 0; s < SPLIT - 1; ++s)
#pragma unroll
            for (int t = 0; t < K2; ++t) {
                unsigned ck = slist[(s * QPB + tq) * K2 + t];
                if (ck < nd[K2-1]) net_insert(nd, ck);
            }

        // nd[0..10] = 11 nearest incl. self. Skip self by index at readout.
        float s1x = 0.f, s1y = 0.f, s1z = 0.f;
        float s2x = 0.f, s2y = 0.f, s2z = 0.f;
#pragma unroll
        for (int t = 0; t < K2; ++t) {
            int idx = (int)(nd[t] & 0x1FFFu);
            if (idx != qi) {
                float4 c = sp[idx];
                s1x += c.x; s1y += c.y; s1z += c.z;
                const float* pp = base2 + 3 * idx;
                s2x += __ldg(pp + 0);
                s2y += __ldg(pp + 1);
                s2z += __ldg(pp + 2);
            }
        }
        float q2x = __ldg(base2 + 3*qi + 0);
        float q2y = __ldg(base2 + 3*qi + 1);
        float q2z = __ldg(base2 + 3*qi + 2);

        const float inv = 1.0f / (float)KNN;
        acc = fabsf((s1x*inv - q.x) - (s2x*inv - q2x))
            + fabsf((s1y*inv - q.y) - (s2y*inv - q2y))
            + fabsf((s1z*inv - q.z) - (s2z*inv - q2z));
    }

    // Deterministic block reduction over 32 warps (non-owner lanes carry 0).
    __syncthreads();
    __shared__ float sred[BLOCK / 32];
#pragma unroll
    for (int o = 16; o > 0; o >>= 1)
        acc += __shfl_down_sync(0xffffffffu, acc, o);
    if ((threadIdx.x & 31) == 0) sred[threadIdx.x >> 5] = acc;
    __syncthreads();
    if (threadIdx.x == 0) {
        float s = 0.f;
#pragma unroll
        for (int w = 0; w < BLOCK / 32; ++w) s += sred[w];
        g_partial[blockIdx.y * BPB + blockIdx.x] = s;
    }
}

__global__ void finalize_kernel(float* __restrict__ out)
{
    __shared__ float s[NBLOCKS];
    int t = threadIdx.x;
    s[t] = g_partial[t];
    __syncthreads();
#pragma unroll
    for (int o = NBLOCKS / 2; o > 0; o >>= 1) {
        if (t < o) s[t] += s[t + o];
        __syncthreads();
    }
    if (t == 0) out[0] = s[0] * (1.0f / (float)(NB * NPTS * 3));
}

extern "C" void kernel_launch(void* const* d_in, const int* in_sizes, int n_in,
                              void* d_out, int out_size)
{
    (void)in_sizes; (void)n_in; (void)out_size;
    const float* p1 = (const float*)d_in[0];
    const float* p2 = (const float*)d_in[1];

    cudaFuncSetAttribute(knn_lap_kernel,
                         cudaFuncAttributeMaxDynamicSharedMemorySize,
                         SMEM_TOTAL);

    dim3 grid(BPB, NB);
    knn_lap_kernel<<<grid, BLOCK, SMEM_TOTAL>>>(p1, p2);
    finalize_kernel<<<1, NBLOCKS>>>((float*)d_out);
}